// round 9
// baseline (speedup 1.0000x reference)
#include <cuda_runtime.h>
#include <cstdint>

// Shapes (fixed):
//   x:   [B=8, 37, 37, 384] fp32, channel-last
//   out: [B, 29*384, 37, 37] fp32; out(b,bin,c,y,x) at ((b*29+bin)*384 + c)*1369 + y*37 + x
//   bins 0..8 : raw shifted by (dy,dx) in {-1,0,1}^2 (row-major), border-clamped
//   bins 9..16: 3x3 avgpool (count_include_pad=False) shifted (dy,dx) in {-3,0,3}^2 \ {0,0}
//   bins 17..28: zeros

#define BATCH 8
#define W 37
#define D 384
#define NBINS 29
#define PLANE (W * W)                    // 1369
#define CHPLANE ((size_t)D * PLANE)      // 525696
#define G 2                              // channels per prep block

#define PADW 44                          // padded row stride; logical x,y in [-3, 39]
#define PADH 43
#define PSZ (PADH * PADW)                // 1892 (divisible by 4)

__device__ __forceinline__ int clampw(int v) { return min(max(v, 0), W - 1); }

// Padded-plane index for logical (y, x), y/x possibly in [-3, W+2].
#define PIDX(y, x) (((y) + 3) * PADW + ((x) + 3))

// Pre-clamped planar scratch: [b][c][PSZ]. 23.25 MB each.
__device__ __align__(16) float g_raw [(size_t)BATCH * D * PSZ];
__device__ __align__(16) float g_pool[(size_t)BATCH * D * PSZ];

// ===========================================================================
// K1: prep. Per block: load G=2 channels, border-replicate, 3x3 pool,
// dump padded raw + pooled planes to global scratch (coalesced float4).
// ===========================================================================
__global__ __launch_bounds__(256) void prep_kernel(const float* __restrict__ in) {
    __shared__ __align__(16) float sr[G][PSZ];
    __shared__ __align__(16) float sp[G][PSZ];

    const int c0 = blockIdx.x * G;
    const int b  = blockIdx.y;
    const int tid = threadIdx.x;

    // Interior load: one float2 LDG per spatial element covers both channels.
    const float2* src2 = reinterpret_cast<const float2*>(in + (size_t)b * PLANE * D + c0);
    for (int i = tid; i < PLANE; i += 256) {
        int y = i / W, x = i - y * W;
        float2 v = src2[(size_t)i * (D / 2)];
        int j = PIDX(y, x);
        sr[0][j] = v.x; sr[1][j] = v.y;
    }
    __syncthreads();

    // Border fill raw (writes borders only) + pool interior (reads interior only).
    for (int t = tid; t < G * PSZ; t += 256) {
        int g = t / PSZ, j = t - g * PSZ;
        int py = j / PADW, px = j - py * PADW;
        if (px > PADH - 1) continue;                    // col 43 unused
        int y = py - 3, x = px - 3;
        if ((unsigned)y < (unsigned)W && (unsigned)x < (unsigned)W) continue;
        sr[g][j] = sr[g][PIDX(clampw(y), clampw(x))];
    }
    for (int t = tid; t < G * PLANE; t += 256) {
        int g = t / PLANE, i = t - g * PLANE;
        int y = i / W, x = i - y * W;
        int y0 = max(y - 1, 0), y1 = min(y + 1, W - 1);
        int x0 = max(x - 1, 0), x1 = min(x + 1, W - 1);
        float s = 0.f;
        for (int yy = y0; yy <= y1; yy++)
            for (int xx = x0; xx <= x1; xx++)
                s += sr[g][PIDX(yy, xx)];
        sp[g][PIDX(y, x)] = s * (1.0f / (float)((y1 - y0 + 1) * (x1 - x0 + 1)));
    }
    __syncthreads();

    // Border fill pooled.
    for (int t = tid; t < G * PSZ; t += 256) {
        int g = t / PSZ, j = t - g * PSZ;
        int py = j / PADW, px = j - py * PADW;
        if (px > PADH - 1) continue;
        int y = py - 3, x = px - 3;
        if ((unsigned)y < (unsigned)W && (unsigned)x < (unsigned)W) continue;
        sp[g][j] = sp[g][PIDX(clampw(y), clampw(x))];
    }
    __syncthreads();

    // Dump both planes (coalesced float4 smem->global).
    const int n4 = PSZ / 4;                             // 473
    for (int t = tid; t < G * n4; t += 256) {
        int g = t / n4, q = t - g * n4;
        size_t pb = ((size_t)b * D + c0 + g) * PSZ;
        reinterpret_cast<float4*>(g_raw  + pb)[q] = reinterpret_cast<const float4*>(sr[g])[q];
        reinterpret_cast<float4*>(g_pool + pb)[q] = reinterpret_cast<const float4*>(sp[g])[q];
    }
}

// ===========================================================================
// K2: fanout. No smem, no syncs. Block = one (b, c) plane; thread = one
// aligned float4 quad (or a head/tail scalar). Gathers are L1-resident LDGs
// with compile-time immediate offsets; 29 STG.128 per quad.
// ===========================================================================
__global__ __launch_bounds__(384) void fanout_kernel(float* __restrict__ out) {
    const int bx = blockIdx.x;
    const int c  = bx % D;
    const int b  = bx / D;
    const int t  = threadIdx.x;

    // Compile-time gather offsets within a padded plane.
    constexpr int roff[9] = { -PADW - 1, -PADW, -PADW + 1,  -1, 0, 1,
                               PADW - 1,  PADW,  PADW + 1 };
    constexpr int poff[8] = { -3 * PADW - 3, -3 * PADW, -3 * PADW + 3,
                              -3, 3,
                               3 * PADW - 3,  3 * PADW,  3 * PADW + 3 };

    const size_t pb = ((size_t)b * D + c) * PSZ;
    const float* __restrict__ ar = g_raw  + pb;
    const float* __restrict__ ap = g_pool + pb;

    const size_t ob = ((size_t)(b * NBINS) * D + c) * PLANE;
    float* const obase = out + ob;
    const int head = (4 - (c & 3)) & 3;                 // ob % 4 == c % 4
    const int nq   = (PLANE - head) >> 2;
    const int tail = (PLANE - head) & 3;

    if (t < nq) {
        const int i0 = head + 4 * t;
        int y0 = i0 / W, x0 = i0 - y0 * W;
        int be[4];
        #pragma unroll
        for (int e = 0; e < 4; e++) {
            int xi = x0 + e, yi = y0;
            if (xi >= W) { xi -= W; yi++; }             // at most one row crossing
            be[e] = PIDX(yi, xi);
        }

        #pragma unroll
        for (int bin = 0; bin < 9; bin++) {
            float4 r;
            r.x = ar[be[0] + roff[bin]];
            r.y = ar[be[1] + roff[bin]];
            r.z = ar[be[2] + roff[bin]];
            r.w = ar[be[3] + roff[bin]];
            *reinterpret_cast<float4*>(obase + (size_t)bin * CHPLANE + i0) = r;
        }
        #pragma unroll
        for (int k = 0; k < 8; k++) {
            float4 r;
            r.x = ap[be[0] + poff[k]];
            r.y = ap[be[1] + poff[k]];
            r.z = ap[be[2] + poff[k]];
            r.w = ap[be[3] + poff[k]];
            *reinterpret_cast<float4*>(obase + (size_t)(9 + k) * CHPLANE + i0) = r;
        }
        const float4 z = make_float4(0.f, 0.f, 0.f, 0.f);
        #pragma unroll
        for (int bin = 17; bin < NBINS; bin++)
            *reinterpret_cast<float4*>(obase + (size_t)bin * CHPLANE + i0) = z;
    } else if (t < nq + head + tail) {
        // Scalar leftovers: head elements [0, head), tail elements [head+4nq, PLANE).
        int k = t - nq;
        int si = (k < head) ? k : (head + 4 * nq + (k - head));
        int y = si / W, x = si - y * W;
        int base = PIDX(y, x);
        #pragma unroll
        for (int bin = 0; bin < 9; bin++)
            obase[(size_t)bin * CHPLANE + si] = ar[base + roff[bin]];
        #pragma unroll
        for (int k2 = 0; k2 < 8; k2++)
            obase[(size_t)(9 + k2) * CHPLANE + si] = ap[base + poff[k2]];
        #pragma unroll
        for (int bin = 17; bin < NBINS; bin++)
            obase[(size_t)bin * CHPLANE + si] = 0.f;
    }
}

// ---------------------------------------------------------------------------
extern "C" void kernel_launch(void* const* d_in, const int* in_sizes, int n_in,
                              void* d_out, int out_size) {
    const float* x = (const float*)d_in[0];
    float* out = (float*)d_out;

    {
        dim3 grid(D / G, BATCH);     // 1536 blocks
        prep_kernel<<<grid, 256>>>(x);
    }
    {
        fanout_kernel<<<D * BATCH, 384>>>(out);   // 3072 blocks
    }
}

// round 10
// speedup vs baseline: 1.0691x; 1.0691x over previous
#include <cuda_runtime.h>
#include <cstdint>

// Shapes (fixed):
//   x:   [B=8, 37, 37, 384] fp32, channel-last
//   out: [B, 29*384, 37, 37] fp32; out(b,bin,c,y,x) at ((b*29+bin)*384 + c)*1369 + y*37 + x
//   bins 0..8 : raw shifted by (dy,dx) in {-1,0,1}^2 (row-major), border-clamped
//   bins 9..16: 3x3 avgpool (count_include_pad=False) shifted (dy,dx) in {-3,0,3}^2 \ {0,0}
//   bins 17..28: zeros

#define BATCH 8
#define W 37
#define D 384
#define NBINS 29
#define PLANE (W * W)                    // 1369
#define CHPLANE ((size_t)D * PLANE)      // 525696
#define G 2                              // channels per prep block

#define PADW 44                          // padded row stride; logical x,y in [-3, 39]
#define PADH 43
#define PSZ (PADH * PADW)                // 1892 (divisible by 4)

#define NPREP ((D / G) * BATCH)          // 1536
#define NZERO 1536
#define NB1 (NPREP + NZERO)              // 3072; even blocks = prep, odd = zero

__device__ __forceinline__ int clampw(int v) { return min(max(v, 0), W - 1); }

// Padded-plane index for logical (y, x), y/x possibly in [-3, W+2].
#define PIDX(y, x) (((y) + 3) * PADW + ((x) + 3))

// Pre-clamped planar scratch: [b][c][PSZ]. 23.25 MB each.
__device__ __align__(16) float g_raw [(size_t)BATCH * D * PSZ];
__device__ __align__(16) float g_pool[(size_t)BATCH * D * PSZ];

// ===========================================================================
// K1: interleaved prep blocks + zero-fill blocks.
//   prep: load G=2 channels, border-replicate, 3x3 pool, dump padded planes.
//   zero: float4 fill of output bins 17..28 (202 MB) — saturates stores while
//         prep blocks sit in their latency-bound phases.
// ===========================================================================
__global__ __launch_bounds__(256) void prep_zero_kernel(const float* __restrict__ in,
                                                        float* __restrict__ out) {
    const int bx  = blockIdx.x;
    const int tid = threadIdx.x;

    if (bx & 1) {
        // ---------------- Zero block ----------------
        const int zid = bx >> 1;                        // 0..NZERO-1
        const size_t plane4 = CHPLANE / 4;
        const size_t len4   = 12 * plane4;              // per batch
        const size_t total  = (size_t)BATCH * len4;
        const float4 z = make_float4(0.f, 0.f, 0.f, 0.f);
        float4* out4 = reinterpret_cast<float4*>(out);
        for (size_t idx = (size_t)zid * 256 + tid; idx < total; idx += (size_t)NZERO * 256) {
            size_t b = idx / len4;
            size_t r = idx - b * len4;
            out4[(b * NBINS + 17) * plane4 + r] = z;
        }
        return;
    }

    // ---------------- Prep block ----------------
    const int pid = bx >> 1;                            // 0..NPREP-1
    const int c0 = (pid % (D / G)) * G;
    const int b  = pid / (D / G);

    __shared__ __align__(16) float sr[G][PSZ];
    __shared__ __align__(16) float sp[G][PSZ];

    // Interior load: one float2 LDG per spatial element covers both channels.
    const float2* src2 = reinterpret_cast<const float2*>(in + (size_t)b * PLANE * D + c0);
    for (int i = tid; i < PLANE; i += 256) {
        int y = i / W, x = i - y * W;
        float2 v = src2[(size_t)i * (D / 2)];
        int j = PIDX(y, x);
        sr[0][j] = v.x; sr[1][j] = v.y;
    }
    __syncthreads();

    // Border fill raw (writes borders only) + pool interior (reads interior only).
    for (int t = tid; t < G * PSZ; t += 256) {
        int g = t / PSZ, j = t - g * PSZ;
        int py = j / PADW, px = j - py * PADW;
        if (px > PADH - 1) continue;                    // col 43 unused
        int y = py - 3, x = px - 3;
        if ((unsigned)y < (unsigned)W && (unsigned)x < (unsigned)W) continue;
        sr[g][j] = sr[g][PIDX(clampw(y), clampw(x))];
    }
    for (int t = tid; t < G * PLANE; t += 256) {
        int g = t / PLANE, i = t - g * PLANE;
        int y = i / W, x = i - y * W;
        int y0 = max(y - 1, 0), y1 = min(y + 1, W - 1);
        int x0 = max(x - 1, 0), x1 = min(x + 1, W - 1);
        float s = 0.f;
        for (int yy = y0; yy <= y1; yy++)
            for (int xx = x0; xx <= x1; xx++)
                s += sr[g][PIDX(yy, xx)];
        sp[g][PIDX(y, x)] = s * (1.0f / (float)((y1 - y0 + 1) * (x1 - x0 + 1)));
    }
    __syncthreads();

    // Border fill pooled.
    for (int t = tid; t < G * PSZ; t += 256) {
        int g = t / PSZ, j = t - g * PSZ;
        int py = j / PADW, px = j - py * PADW;
        if (px > PADH - 1) continue;
        int y = py - 3, x = px - 3;
        if ((unsigned)y < (unsigned)W && (unsigned)x < (unsigned)W) continue;
        sp[g][j] = sp[g][PIDX(clampw(y), clampw(x))];
    }
    __syncthreads();

    // Dump both planes (coalesced float4 smem->global).
    const int n4 = PSZ / 4;                             // 473
    for (int t = tid; t < G * n4; t += 256) {
        int g = t / n4, q = t - g * n4;
        size_t pb = ((size_t)b * D + c0 + g) * PSZ;
        reinterpret_cast<float4*>(g_raw  + pb)[q] = reinterpret_cast<const float4*>(sr[g])[q];
        reinterpret_cast<float4*>(g_pool + pb)[q] = reinterpret_cast<const float4*>(sp[g])[q];
    }
}

// ===========================================================================
// K2: fanout of the 17 filled bins. No smem, no syncs. Block = one (b, c)
// plane; thread = one aligned float4 quad (or a head/tail scalar). Gathers
// are L1/L2-resident LDGs with compile-time immediate offsets.
// ===========================================================================
__global__ __launch_bounds__(384) void fanout_kernel(float* __restrict__ out) {
    const int bx = blockIdx.x;
    const int c  = bx % D;
    const int b  = bx / D;
    const int t  = threadIdx.x;

    constexpr int roff[9] = { -PADW - 1, -PADW, -PADW + 1,  -1, 0, 1,
                               PADW - 1,  PADW,  PADW + 1 };
    constexpr int poff[8] = { -3 * PADW - 3, -3 * PADW, -3 * PADW + 3,
                              -3, 3,
                               3 * PADW - 3,  3 * PADW,  3 * PADW + 3 };

    const size_t pb = ((size_t)b * D + c) * PSZ;
    const float* __restrict__ ar = g_raw  + pb;
    const float* __restrict__ ap = g_pool + pb;

    const size_t ob = ((size_t)(b * NBINS) * D + c) * PLANE;
    float* const obase = out + ob;
    const int head = (4 - (c & 3)) & 3;                 // ob % 4 == c % 4
    const int nq   = (PLANE - head) >> 2;
    const int tail = (PLANE - head) & 3;

    if (t < nq) {
        const int i0 = head + 4 * t;
        int y0 = i0 / W, x0 = i0 - y0 * W;
        int be[4];
        #pragma unroll
        for (int e = 0; e < 4; e++) {
            int xi = x0 + e, yi = y0;
            if (xi >= W) { xi -= W; yi++; }             // at most one row crossing
            be[e] = PIDX(yi, xi);
        }

        #pragma unroll
        for (int bin = 0; bin < 9; bin++) {
            float4 r;
            r.x = ar[be[0] + roff[bin]];
            r.y = ar[be[1] + roff[bin]];
            r.z = ar[be[2] + roff[bin]];
            r.w = ar[be[3] + roff[bin]];
            *reinterpret_cast<float4*>(obase + (size_t)bin * CHPLANE + i0) = r;
        }
        #pragma unroll
        for (int k = 0; k < 8; k++) {
            float4 r;
            r.x = ap[be[0] + poff[k]];
            r.y = ap[be[1] + poff[k]];
            r.z = ap[be[2] + poff[k]];
            r.w = ap[be[3] + poff[k]];
            *reinterpret_cast<float4*>(obase + (size_t)(9 + k) * CHPLANE + i0) = r;
        }
    } else if (t < nq + head + tail) {
        int k = t - nq;
        int si = (k < head) ? k : (head + 4 * nq + (k - head));
        int y = si / W, x = si - y * W;
        int base = PIDX(y, x);
        #pragma unroll
        for (int bin = 0; bin < 9; bin++)
            obase[(size_t)bin * CHPLANE + si] = ar[base + roff[bin]];
        #pragma unroll
        for (int k2 = 0; k2 < 8; k2++)
            obase[(size_t)(9 + k2) * CHPLANE + si] = ap[base + poff[k2]];
    }
}

// ---------------------------------------------------------------------------
extern "C" void kernel_launch(void* const* d_in, const int* in_sizes, int n_in,
                              void* d_out, int out_size) {
    const float* x = (const float*)d_in[0];
    float* out = (float*)d_out;

    prep_zero_kernel<<<NB1, 256>>>(x, out);     // prep + 202 MB zero fill, overlapped
    fanout_kernel<<<D * BATCH, 384>>>(out);     // 285 MB gather/store
}

// round 12
// speedup vs baseline: 1.1307x; 1.0576x over previous
#include <cuda_runtime.h>
#include <cstdint>

// Shapes (fixed):
//   x:   [B=8, 37, 37, 384] fp32, channel-last
//   out: [B, 29*384, 37, 37] fp32; out(b,bin,c,y,x) at ((b*29+bin)*384 + c)*1369 + y*37 + x
//   bins 0..8 : raw shifted by (dy,dx) in {-1,0,1}^2 (row-major), border-clamped
//   bins 9..16: 3x3 avgpool (count_include_pad=False) shifted (dy,dx) in {-3,0,3}^2 \ {0,0}
//   bins 17..28: zeros

#define BATCH 8
#define W 37
#define D 384
#define HALFD 192
#define NBINS 29
#define PLANE (W * W)                    // 1369
#define CHPLANE ((size_t)D * PLANE)      // 525696

#define PADW 44                          // padded row stride; logical x,y in [-3, 39] -> px,py 0..42
#define PADH 43
#define PSZ (PADH * PADW)                // 1892
#define TSTRIDE 193                      // smem transpose tile stride (conflict-free)

#define NZTOT 2720                       // total zero blocks across K1+K2

__device__ __forceinline__ int clampw(int v) { return min(max(v, 0), W - 1); }

// Padded-plane index for logical (y, x), y/x in [-3, W+2].
#define PIDX(y, x) (((y) + 3) * PADW + ((x) + 3))

// Pre-clamped planar scratch: [b*D + c][PSZ]. 23.25 MB each.
__device__ __align__(16) float g_raw [(size_t)BATCH * D * PSZ];
__device__ __align__(16) float g_pool[(size_t)BATCH * D * PSZ];

// ---------------------------------------------------------------------------
// Shared zero-fill worker: zero blocks zid in [0, NZTOT) collectively cover
// output bins 17..28 for all batches with float4 stores.
// ---------------------------------------------------------------------------
__device__ __forceinline__ void zero_work(float* __restrict__ out, int zid, int tid) {
    const size_t plane4 = CHPLANE / 4;
    const size_t len4   = 12 * plane4;              // per batch
    const size_t total  = (size_t)BATCH * len4;
    const float4 z = make_float4(0.f, 0.f, 0.f, 0.f);
    float4* out4 = reinterpret_cast<float4*>(out);
    for (size_t idx = (size_t)zid * 256 + tid; idx < total; idx += (size_t)NZTOT * 256) {
        size_t b = idx / len4;
        size_t r = idx - b * len4;
        out4[(b * NBINS + 17) * plane4 + r] = z;
    }
}

// ===========================================================================
// K1: transpose (channel-last -> padded planar raw, borders included)
//     interleaved 1:2 with zero blocks.
// Transpose block = (y, half, b): smem tile, coalesced both directions.
// ===========================================================================
__global__ __launch_bounds__(256) void transpose_zero_kernel(const float* __restrict__ in,
                                                             float* __restrict__ out) {
    const int bx  = blockIdx.x;
    const int tid = threadIdx.x;

    if (bx % 3 != 0) {
        // zero block: zid = 2*(bx/3) + (bx%3 - 1), range [0, 1184)
        zero_work(out, (bx / 3) * 2 + (bx % 3 - 1), tid);
        return;
    }

    const int tix  = bx / 3;            // 0..591
    const int y    = tix % 37;
    const int rest = tix / 37;
    const int half = rest & 1;
    const int b    = rest >> 1;
    const int c0   = half * HALFD;

    __shared__ float tile[W * TSTRIDE];  // 28564 B

    const float* srcrow = in + ((size_t)(b * W + y) * W) * D + c0;
    for (int t = tid; t < W * HALFD; t += 256) {
        int x = t / HALFD;
        int c = t - x * HALFD;
        tile[x * TSTRIDE + c] = srcrow[(size_t)x * D + c];
    }
    __syncthreads();

    // Write padded row y (+ col borders) of 192 planes; replicate at top/bottom.
    for (int t = tid; t < HALFD * PADH; t += 256) {
        int c  = t / PADH;
        int px = t - c * PADH;                       // 0..42
        int xx = clampw(px - 3);
        float v = tile[xx * TSTRIDE + c];
        float* pl = g_raw + (size_t)(b * D + c0 + c) * PSZ;
        pl[(y + 3) * PADW + px] = v;
        if (y == 0) {
            pl[0 * PADW + px] = v; pl[1 * PADW + px] = v; pl[2 * PADW + px] = v;
        }
        if (y == 36) {
            pl[40 * PADW + px] = v; pl[41 * PADW + px] = v; pl[42 * PADW + px] = v;
        }
    }
}

// ===========================================================================
// K2: planar 3x3 avg pool (count_include_pad=False) with padded-border output,
//     interleaved 1:2 with the remaining zero blocks.
// Pool block = one plane: contiguous reads (L1/L2), contiguous writes.
// ===========================================================================
__global__ __launch_bounds__(256) void pool_zero_kernel(float* __restrict__ out) {
    const int bx  = blockIdx.x;
    const int tid = threadIdx.x;

    if (bx % 3 == 2) {
        // zero block: zid = 1184 + bx/3, range [1184, 2720)
        zero_work(out, 1184 + bx / 3, tid);
        return;
    }

    const int p = bx - (bx + 1) / 3;                 // 0..3071 (plane index b*D+c)
    const float* __restrict__ arp = g_raw  + (size_t)p * PSZ;
    float*       __restrict__ app = g_pool + (size_t)p * PSZ;

    for (int j = tid; j < PSZ; j += 256) {
        int py = j / PADW, px = j - py * PADW;
        int y = clampw(py - 3), x = clampw(px - 3);  // border -> pooled value at clamped pos
        int y0 = max(y - 1, 0), y1 = min(y + 1, W - 1);
        int x0 = max(x - 1, 0), x1 = min(x + 1, W - 1);
        float s = 0.f;
        for (int yy = y0; yy <= y1; yy++)
            for (int xx = x0; xx <= x1; xx++)
                s += arp[PIDX(yy, xx)];
        app[j] = s * (1.0f / (float)((y1 - y0 + 1) * (x1 - x0 + 1)));
    }
}

// ===========================================================================
// K3: fanout of the 17 filled bins (unchanged from R10; measured 57.6 us).
// ===========================================================================
__global__ __launch_bounds__(384) void fanout_kernel(float* __restrict__ out) {
    const int bx = blockIdx.x;
    const int c  = bx % D;
    const int b  = bx / D;
    const int t  = threadIdx.x;

    constexpr int roff[9] = { -PADW - 1, -PADW, -PADW + 1,  -1, 0, 1,
                               PADW - 1,  PADW,  PADW + 1 };
    constexpr int poff[8] = { -3 * PADW - 3, -3 * PADW, -3 * PADW + 3,
                              -3, 3,
                               3 * PADW - 3,  3 * PADW,  3 * PADW + 3 };

    const size_t pb = ((size_t)b * D + c) * PSZ;
    const float* __restrict__ ar = g_raw  + pb;
    const float* __restrict__ ap = g_pool + pb;

    const size_t ob = ((size_t)(b * NBINS) * D + c) * PLANE;
    float* const obase = out + ob;
    const int head = (4 - (c & 3)) & 3;              // ob % 4 == c % 4
    const int nq   = (PLANE - head) >> 2;
    const int tail = (PLANE - head) & 3;

    if (t < nq) {
        const int i0 = head + 4 * t;
        int y0 = i0 / W, x0 = i0 - y0 * W;
        int be[4];
        #pragma unroll
        for (int e = 0; e < 4; e++) {
            int xi = x0 + e, yi = y0;
            if (xi >= W) { xi -= W; yi++; }          // at most one row crossing
            be[e] = PIDX(yi, xi);
        }

        #pragma unroll
        for (int bin = 0; bin < 9; bin++) {
            float4 r;
            r.x = ar[be[0] + roff[bin]];
            r.y = ar[be[1] + roff[bin]];
            r.z = ar[be[2] + roff[bin]];
            r.w = ar[be[3] + roff[bin]];
            *reinterpret_cast<float4*>(obase + (size_t)bin * CHPLANE + i0) = r;
        }
        #pragma unroll
        for (int k = 0; k < 8; k++) {
            float4 r;
            r.x = ap[be[0] + poff[k]];
            r.y = ap[be[1] + poff[k]];
            r.z = ap[be[2] + poff[k]];
            r.w = ap[be[3] + poff[k]];
            *reinterpret_cast<float4*>(obase + (size_t)(9 + k) * CHPLANE + i0) = r;
        }
    } else if (t < nq + head + tail) {
        int k = t - nq;
        int si = (k < head) ? k : (head + 4 * nq + (k - head));
        int y = si / W, x = si - y * W;
        int base = PIDX(y, x);
        #pragma unroll
        for (int bin = 0; bin < 9; bin++)
            obase[(size_t)bin * CHPLANE + si] = ar[base + roff[bin]];
        #pragma unroll
        for (int k2 = 0; k2 < 8; k2++)
            obase[(size_t)(9 + k2) * CHPLANE + si] = ap[base + poff[k2]];
    }
}

// ---------------------------------------------------------------------------
extern "C" void kernel_launch(void* const* d_in, const int* in_sizes, int n_in,
                              void* d_out, int out_size) {
    const float* x = (const float*)d_in[0];
    float* out = (float*)d_out;

    transpose_zero_kernel<<<1776, 256>>>(x, out);   // 592 transpose + 1184 zero
    pool_zero_kernel<<<4608, 256>>>(out);           // 3072 pool + 1536 zero
    fanout_kernel<<<D * BATCH, 384>>>(out);         // 285 MB gather/store
}

// round 13
// speedup vs baseline: 1.3220x; 1.1691x over previous
#include <cuda_runtime.h>
#include <cstdint>

// Shapes (fixed):
//   x:   [B=8, 37, 37, 384] fp32, channel-last
//   out: [B, 29*384, 37, 37] fp32; out(b,bin,c,y,x) at ((b*29+bin)*384 + c)*1369 + y*37 + x
//   bins 0..8 : raw shifted by (dy,dx) in {-1,0,1}^2 (row-major), border-clamped
//   bins 9..16: 3x3 avgpool (count_include_pad=False) shifted (dy,dx) in {-3,0,3}^2 \ {0,0}
//   bins 17..28: zeros

#define BATCH 8
#define W 37
#define D 384
#define NBINS 29
#define PLANE (W * W)                    // 1369
#define CHPLANE ((size_t)D * PLANE)      // 525696
#define G 2                              // channels per gather block

#define PADW 44                          // padded row stride; logical x,y in [-3, 39]
#define PADH 43
#define PSZ (PADH * PADW)                // 1892 (divisible by 4)

#define NGATHER ((D / G) * BATCH)        // 1536
#define NZERO 1152                       // zero blocks; 12*CHPLANE/4 = 1577088 = 1152/8*... (144 per batch)
#define ZCHUNK 10952                     // float4s per zero block: 1577088 / 144
#define NBLK (NGATHER + NZERO)           // 2688; bx%7<4 -> gather, else zero

__device__ __forceinline__ int clampw(int v) { return min(max(v, 0), W - 1); }

// Padded-plane index for logical (y, x), y/x in [-3, W+2].
#define PIDX(y, x) (((y) + 3) * PADW + ((x) + 3))

// Pre-clamped planar scratch: [b*D + c][PSZ]. 23.25 MB each.
__device__ __align__(16) float g_raw [(size_t)BATCH * D * PSZ];
__device__ __align__(16) float g_pool[(size_t)BATCH * D * PSZ];

__global__ __launch_bounds__(384) void fused_kernel(const float* __restrict__ in,
                                                    float* __restrict__ out) {
    const int bx  = blockIdx.x;
    const int tid = threadIdx.x;
    const int m   = bx % 7;

    // ================= Zero blocks: division-free contiguous float4 fill =================
    if (m >= 4) {
        const int zid = (bx / 7) * 3 + (m - 4);            // 0..NZERO-1
        const int zb  = zid / 144;                         // batch
        const int p   = zid - zb * 144;                    // portion within batch
        const size_t plane4 = CHPLANE / 4;
        float4* dst = reinterpret_cast<float4*>(out) +
                      ((size_t)zb * NBINS + 17) * plane4 + (size_t)p * ZCHUNK;
        const float4 z = make_float4(0.f, 0.f, 0.f, 0.f);
        for (int k = tid; k < ZCHUNK; k += 384)
            dst[k] = z;
        return;
    }

    // ================= Gather blocks =================
    const int gidx = (bx / 7) * 4 + m;                     // 0..NGATHER-1
    const int c0 = (gidx % (D / G)) * G;
    const int b  = gidx / (D / G);

    __shared__ __align__(16) float sr[G][PSZ];
    __shared__ __align__(16) float sp[G][PSZ];

    // ---- Load interior: one float2 LDG per spatial element covers both channels ----
    const float2* src2 = reinterpret_cast<const float2*>(in + (size_t)b * PLANE * D + c0);
    for (int i = tid; i < PLANE; i += 384) {
        int y = i / W, x = i - y * W;
        float2 v = src2[(size_t)i * (D / 2)];
        int j = PIDX(y, x);
        sr[0][j] = v.x; sr[1][j] = v.y;
    }
    __syncthreads();

    // ---- Border-fill raw (writes borders only) + 3x3 pool interior ----
    for (int t = tid; t < G * PSZ; t += 384) {
        int g = t / PSZ, j = t - g * PSZ;
        int py = j / PADW, px = j - py * PADW;
        if (px > PADH - 1) continue;                       // col 43 unused
        int y = py - 3, x = px - 3;
        if ((unsigned)y < (unsigned)W && (unsigned)x < (unsigned)W) continue;
        sr[g][j] = sr[g][PIDX(clampw(y), clampw(x))];
    }
    for (int t = tid; t < G * PLANE; t += 384) {
        int g = t / PLANE, i = t - g * PLANE;
        int y = i / W, x = i - y * W;
        int y0 = max(y - 1, 0), y1 = min(y + 1, W - 1);
        int x0 = max(x - 1, 0), x1 = min(x + 1, W - 1);
        float s = 0.f;
        for (int yy = y0; yy <= y1; yy++)
            for (int xx = x0; xx <= x1; xx++)
                s += sr[g][PIDX(yy, xx)];
        sp[g][PIDX(y, x)] = s * (1.0f / (float)((y1 - y0 + 1) * (x1 - x0 + 1)));
    }
    __syncthreads();

    // ---- Border-fill pooled ----
    for (int t = tid; t < G * PSZ; t += 384) {
        int g = t / PSZ, j = t - g * PSZ;
        int py = j / PADW, px = j - py * PADW;
        if (px > PADH - 1) continue;
        int y = py - 3, x = px - 3;
        if ((unsigned)y < (unsigned)W && (unsigned)x < (unsigned)W) continue;
        sp[g][j] = sp[g][PIDX(clampw(y), clampw(x))];
    }
    __syncthreads();

    // ---- Dump padded planes to own global scratch (coalesced float4) ----
    const int n4 = PSZ / 4;                                // 473
    for (int t = tid; t < G * n4; t += 384) {
        int g = t / n4, q = t - g * n4;
        size_t pb = ((size_t)b * D + c0 + g) * PSZ;
        reinterpret_cast<float4*>(g_raw  + pb)[q] = reinterpret_cast<const float4*>(sr[g])[q];
        reinterpret_cast<float4*>(g_pool + pb)[q] = reinterpret_cast<const float4*>(sp[g])[q];
    }
    __syncthreads();   // own global writes now visible to all threads of this block

    // ---- Gather + store 17 bins per channel: LDG with immediate offsets (K3 engine) ----
    constexpr int roff[9] = { -PADW - 1, -PADW, -PADW + 1,  -1, 0, 1,
                               PADW - 1,  PADW,  PADW + 1 };
    constexpr int poff[8] = { -3 * PADW - 3, -3 * PADW, -3 * PADW + 3,
                              -3, 3,
                               3 * PADW - 3,  3 * PADW,  3 * PADW + 3 };

    #pragma unroll 1
    for (int g = 0; g < G; g++) {
        const int c = c0 + g;
        const size_t pb = ((size_t)b * D + c) * PSZ;
        const float* __restrict__ ar = g_raw  + pb;
        const float* __restrict__ ap = g_pool + pb;

        const size_t ob = ((size_t)(b * NBINS) * D + c) * PLANE;
        float* const obase = out + ob;
        const int head = (4 - (c & 3)) & 3;                // ob % 4 == c % 4
        const int nq   = (PLANE - head) >> 2;
        const int tail = (PLANE - head) & 3;

        if (tid < nq) {
            const int i0 = head + 4 * tid;
            int y0 = i0 / W, x0 = i0 - y0 * W;
            int be[4];
            #pragma unroll
            for (int e = 0; e < 4; e++) {
                int xi = x0 + e, yi = y0;
                if (xi >= W) { xi -= W; yi++; }            // at most one row crossing
                be[e] = PIDX(yi, xi);
            }

            #pragma unroll
            for (int bin = 0; bin < 9; bin++) {
                float4 r;
                r.x = ar[be[0] + roff[bin]];
                r.y = ar[be[1] + roff[bin]];
                r.z = ar[be[2] + roff[bin]];
                r.w = ar[be[3] + roff[bin]];
                *reinterpret_cast<float4*>(obase + (size_t)bin * CHPLANE + i0) = r;
            }
            #pragma unroll
            for (int k = 0; k < 8; k++) {
                float4 r;
                r.x = ap[be[0] + poff[k]];
                r.y = ap[be[1] + poff[k]];
                r.z = ap[be[2] + poff[k]];
                r.w = ap[be[3] + poff[k]];
                *reinterpret_cast<float4*>(obase + (size_t)(9 + k) * CHPLANE + i0) = r;
            }
        } else if (tid < nq + head + tail) {
            int k = tid - nq;
            int si = (k < head) ? k : (head + 4 * nq + (k - head));
            int y = si / W, x = si - y * W;
            int base = PIDX(y, x);
            #pragma unroll
            for (int bin = 0; bin < 9; bin++)
                obase[(size_t)bin * CHPLANE + si] = ar[base + roff[bin]];
            #pragma unroll
            for (int k2 = 0; k2 < 8; k2++)
                obase[(size_t)(9 + k2) * CHPLANE + si] = ap[base + poff[k2]];
        }
    }
}

// ---------------------------------------------------------------------------
extern "C" void kernel_launch(void* const* d_in, const int* in_sizes, int n_in,
                              void* d_out, int out_size) {
    const float* x = (const float*)d_in[0];
    float* out = (float*)d_out;
    fused_kernel<<<NBLK, 384>>>(x, out);
}

// round 15
// speedup vs baseline: 1.4035x; 1.0617x over previous
#include <cuda_runtime.h>
#include <cstdint>

// Shapes (fixed):
//   x:   [B=8, 37, 37, 384] fp32, channel-last
//   out: [B, 29*384, 37, 37] fp32; out(b,bin,c,y,x) at ((b*29+bin)*384 + c)*1369 + y*37 + x
//   bins 0..8 : raw shifted by (dy,dx) in {-1,0,1}^2 (row-major), border-clamped
//   bins 9..16: 3x3 avgpool (count_include_pad=False) shifted (dy,dx) in {-3,0,3}^2 \ {0,0}
//   bins 17..28: zeros

#define BATCH 8
#define W 37
#define D 384
#define NBINS 29
#define PLANE (W * W)                    // 1369
#define CHPLANE ((size_t)D * PLANE)      // 525696
#define G 2                              // channels per gather block

#define PADW 44                          // padded row stride; logical x,y in [-3, 39]
#define PADH 43
#define PSZ (PADH * PADW)                // 1892
#define SWZ(j) ((j) + ((j) >> 5))        // stride-4 lane access -> conflict-free
#define SPSZ (PSZ + (PSZ >> 5) + 4)      // 1955

#define NGATHER ((D / G) * BATCH)        // 1536
#define NZERO   768
#define NBLOCKS (NGATHER + NZERO)        // 2304; every 3rd block (bx%3==2) is a zero block

// Zero-fill geometry: 12 bins * CHPLANE floats per batch = 1,577,088 float4s per batch.
// 1,577,088 = 96 * 16,428  ->  96 zero blocks per batch, each a contiguous 16,428-float4 run.
#define ZPB    96                        // zero blocks per batch (NZERO = 8 * 96)
#define ZCHUNK 16428                     // float4s per zero block (exact)

__device__ __forceinline__ int clampw(int v) { return min(max(v, 0), W - 1); }

// Padded-plane index for logical (y, x) with y,x possibly in [-3, W+2].
#define PIDX(y, x) (((y) + 3) * PADW + ((x) + 3))

__device__ __constant__ int c_off[17] = {
    // raw bins: dy*PADW + dx for (dy,dx) in {-1,0,1}^2 row-major
    -PADW - 1, -PADW, -PADW + 1,  -1, 0, 1,  PADW - 1, PADW, PADW + 1,
    // pooled bins: (dy,dx) in {-3,0,3}^2 minus center
    -3 * PADW - 3, -3 * PADW, -3 * PADW + 3,  -3, 3,  3 * PADW - 3, 3 * PADW, 3 * PADW + 3
};

__global__ __launch_bounds__(256) void fanout_kernel(const float* __restrict__ in,
                                                     float* __restrict__ out) {
    const int bx  = blockIdx.x;
    const int tid = threadIdx.x;

    // ------------- Zero blocks: division-free contiguous float4 fill -------------
    if (bx % 3 == 2) {
        const int zid = bx / 3;                        // 0..NZERO-1
        const int zb  = zid / ZPB;                     // batch (const 32-bit div -> mul/shift)
        const int p   = zid - zb * ZPB;                // chunk within batch
        const size_t plane4 = CHPLANE / 4;
        float4* dst = reinterpret_cast<float4*>(out) +
                      ((size_t)zb * NBINS + 17) * plane4 + (size_t)p * ZCHUNK;
        const float4 z = make_float4(0.f, 0.f, 0.f, 0.f);
        for (int k = tid; k < ZCHUNK; k += 256)
            dst[k] = z;
        return;
    }

    // ---------------- Gather blocks ----------------
    const int gidx = bx - bx / 3;                      // 0..NGATHER-1
    const int c0 = (gidx % (D / G)) * G;
    const int b  = gidx / (D / G);

    __shared__ float sr[G][SPSZ];   // padded pre-clamped raw planes (swizzled)
    __shared__ float sp[G][SPSZ];   // padded pre-clamped pooled planes (swizzled)

    // Load interior: 2 channels per spatial element with one float2 LDG.
    const float2* src2 = reinterpret_cast<const float2*>(in + (size_t)b * PLANE * D + c0);
    for (int i = tid; i < PLANE; i += 256) {
        int y = i / W, x = i - y * W;
        float2 v = src2[(size_t)i * (D / 2)];
        int js = SWZ(PIDX(y, x));
        sr[0][js] = v.x; sr[1][js] = v.y;
    }
    __syncthreads();

    // Border-fill raw planes (writes borders only) + 3x3 pool interior.
    for (int t = tid; t < G * PSZ; t += 256) {
        int g = t / PSZ, j = t - g * PSZ;
        int py = j / PADW, px = j - py * PADW;
        if (px > PADH - 1) continue;                   // col 43 unused
        int y = py - 3, x = px - 3;
        if ((unsigned)y < (unsigned)W && (unsigned)x < (unsigned)W) continue;
        sr[g][SWZ(j)] = sr[g][SWZ(PIDX(clampw(y), clampw(x)))];
    }
    for (int t = tid; t < G * PLANE; t += 256) {
        int g = t / PLANE, i = t - g * PLANE;
        int y = i / W, x = i - y * W;
        int y0 = max(y - 1, 0), y1 = min(y + 1, W - 1);
        int x0 = max(x - 1, 0), x1 = min(x + 1, W - 1);
        float s = 0.f;
        for (int yy = y0; yy <= y1; yy++)
            for (int xx = x0; xx <= x1; xx++)
                s += sr[g][SWZ(PIDX(yy, xx))];
        sp[g][SWZ(PIDX(y, x))] = s * (1.0f / (float)((y1 - y0 + 1) * (x1 - x0 + 1)));
    }
    __syncthreads();

    // Border-fill pooled planes.
    for (int t = tid; t < G * PSZ; t += 256) {
        int g = t / PSZ, j = t - g * PSZ;
        int py = j / PADW, px = j - py * PADW;
        if (px > PADH - 1) continue;
        int y = py - 3, x = px - 3;
        if ((unsigned)y < (unsigned)W && (unsigned)x < (unsigned)W) continue;
        sp[g][SWZ(j)] = sp[g][SWZ(PIDX(clampw(y), clampw(x)))];
    }
    __syncthreads();

    // Gather + store 17 bins per channel. Channel loop kept rolled for regs.
    #pragma unroll 1
    for (int g = 0; g < G; g++) {
        const float* __restrict__ a_r = sr[g];
        const float* __restrict__ a_p = sp[g];

        const size_t ob = ((size_t)(b * NBINS) * D + (c0 + g)) * PLANE;
        float* const obase = out + ob;
        const int phase = (int)(ob & 3);
        const int head  = (4 - phase) & 3;
        const int nq    = (PLANE - head) >> 2;
        const int tail  = (PLANE - head) & 3;

        // Body: 16B-aligned float4 quads (CHPLANE % 4 == 0 keeps all bins aligned).
        for (int q = tid; q < nq; q += 256) {
            const int i0 = head + 4 * q;
            int y0 = i0 / W, x0 = i0 - y0 * W;
            int be[4];
            #pragma unroll
            for (int e = 0; e < 4; e++) {
                int xi = x0 + e, yi = y0;
                if (xi >= W) { xi -= W; yi++; }        // at most one row crossing
                be[e] = PIDX(yi, xi);
            }

            #pragma unroll
            for (int bin = 0; bin < 17; bin++) {
                const float* a = (bin < 9) ? a_r : a_p;
                const int off = c_off[bin];
                float4 r;
                r.x = a[SWZ(be[0] + off)];
                r.y = a[SWZ(be[1] + off)];
                r.z = a[SWZ(be[2] + off)];
                r.w = a[SWZ(be[3] + off)];
                *reinterpret_cast<float4*>(obase + (size_t)bin * CHPLANE + i0) = r;
            }
        }

        // Head/tail scalars.
        int si = -1;
        if (tid < head)
            si = tid;
        else if (tid >= 32 && tid < 32 + tail)
            si = head + 4 * nq + (tid - 32);
        if (si >= 0) {
            int y = si / W, x = si - y * W;
            int base = PIDX(y, x);
            #pragma unroll
            for (int bin = 0; bin < 17; bin++) {
                const float* a = (bin < 9) ? a_r : a_p;
                obase[(size_t)bin * CHPLANE + si] = a[SWZ(base + c_off[bin])];
            }
        }
    }
}

// ---------------------------------------------------------------------------
extern "C" void kernel_launch(void* const* d_in, const int* in_sizes, int n_in,
                              void* d_out, int out_size) {
    const float* x = (const float*)d_in[0];
    float* out = (float*)d_out;
    fanout_kernel<<<NBLOCKS, 256>>>(x, out);
}